// round 4
// baseline (speedup 1.0000x reference)
#include <cuda_runtime.h>

#define NB 4
#define LL 4096
#define ND 8
#define KMAX 64
#define NCODES 256

// Scratch (no allocations allowed): per-(batch,code) result rows, 256 KB.
// Output dtype is float32 (indices -1..4095 stored exactly as floats).
__device__ float g_rows[NB * NCODES * KMAX];

// K1: one warp per (batch, code); 8 codes per 256-thread block, 32 blocks/batch.
// Each block packs its batch's 4096 key codes into smem, then each warp does a
// stable first-64 match scan via ballot + prefix-popc (ascending j for free),
// and emits the sorted row: (64-m) leading -1s then the m matches ascending
// (matches jnp.sort of the -1-padded candidate list exactly).
__global__ void k_build_rows(const float* __restrict__ key_up) {
    __shared__ int sc[LL];          // 16 KB: this batch's key codes
    __shared__ int buf[8][KMAX];    // per-warp match buffer

    int b    = blockIdx.x >> 5;     // 32 blocks per batch
    int cg   = blockIdx.x & 31;     // code group (8 codes per block)
    int tid  = threadIdx.x;
    int warp = tid >> 5;
    int lane = tid & 31;

    // Pack codes for this batch: bit d = (x[d] > 0), weight 2^d.
    const float4* kb = reinterpret_cast<const float4*>(key_up + (long long)b * LL * ND);
    for (int j = tid; j < LL; j += 256) {
        float4 a = kb[j * 2];
        float4 c = kb[j * 2 + 1];
        sc[j] = (a.x > 0.f)        | ((a.y > 0.f) << 1) |
                ((a.z > 0.f) << 2) | ((a.w > 0.f) << 3) |
                ((c.x > 0.f) << 4) | ((c.y > 0.f) << 5) |
                ((c.z > 0.f) << 6) | ((c.w > 0.f) << 7);
    }
    __syncthreads();

    int c = cg * 8 + warp;
    unsigned lt = (1u << lane) - 1u;
    int m = 0;
    for (int base = 0; base < LL; base += 32) {
        int cj = sc[base + lane];
        unsigned mask = __ballot_sync(0xffffffffu, cj == c);
        if (mask) {
            int pos = m + __popc(mask & lt);
            if (((mask >> lane) & 1u) && pos < KMAX)
                buf[warp][pos] = base + lane;     // ascending j guaranteed
            m += __popc(mask);                    // warp-uniform
            if (m >= KMAX) break;                 // warp-uniform
        }
    }
    int mm  = m < KMAX ? m : KMAX;
    int pad = KMAX - mm;
    float* row = g_rows + (((b << 8) + c) * KMAX);
    #pragma unroll
    for (int k = lane; k < KMAX; k += 32)
        row[k] = (k < pad) ? -1.0f : (float)buf[warp][k - pad];
}

// K2: one warp per query. Ballot-pack the query code from 8 floats, then copy
// the precomputed 256B row with one 8B move per lane (fully coalesced).
__global__ void k_emit(const float* __restrict__ query_up,
                       float* __restrict__ out) {
    int gw   = (blockIdx.x * blockDim.x + threadIdx.x) >> 5;  // query id
    if (gw >= NB * LL) return;
    int lane = threadIdx.x & 31;
    int b    = gw >> 12;                                      // / 4096

    const float* q = query_up + gw * ND;
    float v = (lane < ND) ? q[lane] : 0.f;
    unsigned code = __ballot_sync(0xffffffffu, v > 0.f) & 0xffu;

    const float2* src = reinterpret_cast<const float2*>(g_rows + (((b << 8) + (int)code) * KMAX));
    float2*       dst = reinterpret_cast<float2*>(out + (long long)gw * KMAX);
    dst[lane] = src[lane];   // 32 lanes x 8B = 256B row
}

extern "C" void kernel_launch(void* const* d_in, const int* in_sizes, int n_in,
                              void* d_out, int out_size) {
    // Identify inputs by element count, robust to metadata ordering:
    // the two (B*L*D)=131072-element float buffers are query_up then key_up
    // (relative order preserved); the 1-element buffer is head_idx (unused).
    const float* query_up = nullptr;
    const float* key_up   = nullptr;
    for (int i = 0; i < n_in; i++) {
        if (in_sizes[i] == NB * LL * ND) {
            if (!query_up)      query_up = (const float*)d_in[i];
            else if (!key_up)   key_up   = (const float*)d_in[i];
        }
    }
    if (!query_up || !key_up) {     // fallback: assume declared order
        query_up = (const float*)d_in[0];
        key_up   = (const float*)d_in[1];
    }
    float* out = (float*)d_out;

    k_build_rows<<<NB * 32, 256>>>(key_up);                  // 128 blocks
    k_emit<<<(NB * LL * 32) / 1024, 1024>>>(query_up, out);  // 512 blocks
}

// round 5
// speedup vs baseline: 1.3434x; 1.3434x over previous
#include <cuda_runtime.h>

#define NB 4
#define LL 4096
#define ND 8
#define KMAX 64
#define NCODES 256

// Scratch (no allocations): per-(batch,code) result rows, 256 KB, float32.
__device__ float g_rows[NB * NCODES * KMAX];

__device__ __forceinline__ int pack8(float4 a, float4 c) {
    return (a.x > 0.f)        | ((a.y > 0.f) << 1) |
           ((a.z > 0.f) << 2) | ((a.w > 0.f) << 3) |
           ((c.x > 0.f) << 4) | ((c.y > 0.f) << 5) |
           ((c.z > 0.f) << 6) | ((c.w > 0.f) << 7);
}

// K1: one warp per (batch, code); 8 codes per 256-thread block, 32 blocks/batch.
// Pack batch codes to smem, then each warp does a stable first-64 scan
// processing 128 codes per round (int4 per lane, 4 ballots). No early break:
// rounds are independent -> fully pipelined. pos<KMAX predicate guards writes.
__global__ void k_build_rows(const float* __restrict__ key_up) {
    __shared__ int4 sc4[LL / 4];    // 16 KB: this batch's key codes
    __shared__ int  buf[8][KMAX];   // per-warp match buffer

    int b    = blockIdx.x >> 5;
    int cg   = blockIdx.x & 31;
    int tid  = threadIdx.x;
    int warp = tid >> 5;
    int lane = tid & 31;
    int* sc  = reinterpret_cast<int*>(sc4);

    const float4* kb = reinterpret_cast<const float4*>(key_up + (size_t)b * LL * ND);
    #pragma unroll
    for (int it = 0; it < 16; it++) {
        int j = tid + it * 256;
        sc[j] = pack8(kb[j * 2], kb[j * 2 + 1]);
    }
    __syncthreads();

    int c = cg * 8 + warp;
    unsigned lt = (1u << lane) - 1u;
    int m = 0;
    #pragma unroll 4
    for (int r = 0; r < 32; r++) {
        int4 v = sc4[r * 32 + lane];
        unsigned m0 = __ballot_sync(0xffffffffu, v.x == c);
        unsigned m1 = __ballot_sync(0xffffffffu, v.y == c);
        unsigned m2 = __ballot_sync(0xffffffffu, v.z == c);
        unsigned m3 = __ballot_sync(0xffffffffu, v.w == c);
        int p = m + __popc(m0 & lt) + __popc(m1 & lt)
                  + __popc(m2 & lt) + __popc(m3 & lt);
        int j0 = (r * 32 + lane) * 4;
        if (v.x == c) { if (p < KMAX) buf[warp][p] = j0;     p++; }
        if (v.y == c) { if (p < KMAX) buf[warp][p] = j0 + 1; p++; }
        if (v.z == c) { if (p < KMAX) buf[warp][p] = j0 + 2; p++; }
        if (v.w == c) { if (p < KMAX) buf[warp][p] = j0 + 3; p++; }
        m += __popc(m0) + __popc(m1) + __popc(m2) + __popc(m3);
    }
    __syncwarp();

    int mm  = m < KMAX ? m : KMAX;
    int pad = KMAX - mm;
    float* row = g_rows + (((b << 8) + c) * KMAX);
    #pragma unroll
    for (int k = lane; k < KMAX; k += 32)
        row[k] = (k < pad) ? -1.0f : (float)buf[warp][k - pad];
}

// K2: 4 queries per warp. Lanes 0-3 compute the 4 codes arithmetically
// (2x float4 loads each, 128B contiguous per warp), shfl-broadcast to 8-lane
// groups; each group copies its 256B row with 2x float4 per lane, fully
// coalesced on both the L2-resident row read and the DRAM output write.
__global__ void k_emit(const float* __restrict__ query_up,
                       float* __restrict__ out) {
    int gw   = (blockIdx.x * blockDim.x + threadIdx.x) >> 5;  // warp id 0..4095
    int lane = threadIdx.x & 31;

    int code = 0;
    if (lane < 4) {
        const float4* p = reinterpret_cast<const float4*>(query_up) + (gw * 4 + lane) * 2;
        code = pack8(p[0], p[1]);
    }
    int g  = lane >> 3;                       // group 0..3
    int c  = __shfl_sync(0xffffffffu, code, g);
    int qi = gw * 4 + g;                      // query id
    int b  = qi >> 12;                        // / 4096

    const float4* src = reinterpret_cast<const float4*>(g_rows + (((b << 8) + c) * KMAX));
    float4*       dst = reinterpret_cast<float4*>(out + (size_t)qi * KMAX);
    int o = lane & 7;                         // 8 lanes x 2 float4 = 256B row
    float4 v0 = src[o];
    float4 v1 = src[o + 8];
    dst[o]     = v0;
    dst[o + 8] = v1;
}

extern "C" void kernel_launch(void* const* d_in, const int* in_sizes, int n_in,
                              void* d_out, int out_size) {
    // Identify inputs by element count (robust to metadata ordering).
    const float* query_up = nullptr;
    const float* key_up   = nullptr;
    for (int i = 0; i < n_in; i++) {
        if (in_sizes[i] == NB * LL * ND) {
            if (!query_up)      query_up = (const float*)d_in[i];
            else if (!key_up)   key_up   = (const float*)d_in[i];
        }
    }
    if (!query_up || !key_up) {
        query_up = (const float*)d_in[0];
        key_up   = (const float*)d_in[1];
    }
    float* out = (float*)d_out;

    k_build_rows<<<NB * 32, 256>>>(key_up);        // 128 blocks, 1024 warps
    k_emit<<<512, 256>>>(query_up, out);           // 4096 warps, 1 wave
}